// round 11
// baseline (speedup 1.0000x reference)
#include <cuda_runtime.h>
#include <cuda_bf16.h>
#include <math.h>
#include <cstdint>

typedef unsigned long long u64;

// Problem dims (fixed by the dataset)
#define Bc   8
#define Cc   512
#define Hc   96
#define Wc   144
#define HWc  (Hc * Wc)          // 13824
#define Ntok (Bc * HWc)         // 110592
#define Dd   512
#define Mm   512

#define BK     16
#define AS_LD  68               // duplicated-A row stride (floats); 272B = 16B-aligned
#define BS_LD  516              // padded B row stride (floats); 2064B, 16B-aligned
#define A_BUF  (BK * AS_LD)     // 1088 floats per A buffer
#define B_BUF  (BK * BS_LD)     // 8256 floats per B buffer
#define EXTRA_OFF (2 * A_BUF + 2 * B_BUF)   // 18688 floats
#define SMEM_DYN  ((EXTRA_OFF + 1600) * 4)  // 81152 B

// Packed fp32x2 FMA (Blackwell FFMA2 — only reachable via PTX)
#define FMA_F32X2(d, a, b, c) \
    asm("fma.rn.f32x2 %0, %1, %2, %3;" : "=l"(d) : "l"(a), "l"(b), "l"(c))
#define UNPACK_F32X2(lo, hi, in) \
    asm("mov.b64 {%0, %1}, %2;" : "=r"(lo), "=r"(hi) : "l"(in))

#define CP_ASYNC16(dst, src) \
    asm volatile("cp.async.ca.shared.global [%0], [%1], 16;" :: "r"(dst), "l"(src))
#define CP_COMMIT()  asm volatile("cp.async.commit_group;" ::: "memory")
#define CP_WAIT0()   asm volatile("cp.async.wait_group 0;" ::: "memory")

__device__ __forceinline__ uint32_t smem_u32(const void* p) {
    uint32_t a;
    asm("{ .reg .u64 t; cvta.to.shared.u64 t, %1; cvt.u32.u64 %0, t; }"
        : "=r"(a) : "l"(p));
    return a;
}

// Scratch (allocation-free rule: __device__ globals)
__device__ float g_q[(size_t)Ntok * Dd];   // normalized q, [N, D] row-major
__device__ float g_memT[Dd * Mm];          // memory transposed: [d][m]
__device__ float g_inv[Ntok];              // 1/norm per token
__device__ float g_rowsum[Ntok];           // row softmax denominators
__device__ float g_colsum[Mm];             // column softmax denominators

// ---------------------------------------------------------------------------
// K1: per-token inverse L2 norm over channels (coalesced along hw), + zero colsum
// ---------------------------------------------------------------------------
__global__ void k_norm(const float* __restrict__ x) {
    int n = blockIdx.x * 256 + threadIdx.x;
    if (blockIdx.x == 0) {                 // zero ALL 512 entries (idempotent state)
        g_colsum[threadIdx.x]       = 0.0f;
        g_colsum[threadIdx.x + 256] = 0.0f;
    }
    if (n >= Ntok) return;
    int b = n / HWc, hw = n % HWc;
    const float* p = x + (size_t)b * Cc * HWc + hw;
    float s = 0.0f;
#pragma unroll 8
    for (int c = 0; c < Cc; c++) {
        float v = p[(size_t)c * HWc];
        s += v * v;
    }
    g_inv[n] = 1.0f / fmaxf(sqrtf(s), 1e-12f);
}

// ---------------------------------------------------------------------------
// K2: transpose mem [m][d] -> g_memT [d][m] (one-time, 1MB)
// ---------------------------------------------------------------------------
__global__ void k_prepT(const float* __restrict__ pmem) {
    __shared__ float t[32][33];
    int d0 = blockIdx.x * 32;
    int m0 = blockIdx.y * 32;
    for (int r = threadIdx.y; r < 32; r += 8)
        t[r][threadIdx.x] = pmem[(size_t)(m0 + r) * Dd + d0 + threadIdx.x];
    __syncthreads();
    for (int r = threadIdx.y; r < 32; r += 8)
        g_memT[(size_t)(d0 + r) * Mm + m0 + threadIdx.x] = t[threadIdx.x][r];
}

// ---------------------------------------------------------------------------
// K3: transpose [B,C,HW] -> g_q [N,D] with normalization, 32x32 smem tiles
// ---------------------------------------------------------------------------
__global__ void k_qt(const float* __restrict__ x) {
    __shared__ float tile[32][33];
    int b   = blockIdx.z;
    int hw0 = blockIdx.x * 32;
    int d0  = blockIdx.y * 32;
    for (int r = threadIdx.y; r < 32; r += 8)
        tile[r][threadIdx.x] =
            x[((size_t)(b * Cc + d0 + r)) * HWc + hw0 + threadIdx.x];
    __syncthreads();
    for (int r = threadIdx.y; r < 32; r += 8) {
        int n = b * HWc + hw0 + r;
        g_q[(size_t)n * Dd + d0 + threadIdx.x] = tile[threadIdx.x][r] * g_inv[n];
    }
}

// ---------------------------------------------------------------------------
// FFMA2 compute for one BK=16 k-step. Micro-tile: 16 tokens x 4 slots.
// B: 2 LDS.64 (512B distinct/warp/kk, was 1024); A: 8 broadcast LDS.128.
// acc2[i][0] = slots (2sg, 2sg+1); acc2[i][1] = slots (256+2sg, 256+2sg+1).
// ---------------------------------------------------------------------------
#define COMPUTE_KSTEP(As2, Bs, acc2, tg, sg)                                   \
    _Pragma("unroll")                                                          \
    for (int kk = 0; kk < BK; kk++) {                                          \
        u64 b0 = *(const u64*)&(Bs)[kk][(sg) * 2];                             \
        u64 b1 = *(const u64*)&(Bs)[kk][256 + (sg) * 2];                       \
        u64 aa[16];                                                            \
        _Pragma("unroll")                                                      \
        for (int q = 0; q < 8; q++) {                                          \
            double2 ad = *(const double2*)&(As2)[kk][(tg) * 32 + q * 4];       \
            aa[2 * q]     = __double_as_longlong(ad.x);                        \
            aa[2 * q + 1] = __double_as_longlong(ad.y);                        \
        }                                                                      \
        _Pragma("unroll")                                                      \
        for (int i = 0; i < 16; i++) {                                         \
            FMA_F32X2(acc2[i][0], aa[i], b0, acc2[i][0]);                      \
            FMA_F32X2(acc2[i][1], aa[i], b1, acc2[i][1]);                      \
        }                                                                      \
    }

// ---------------------------------------------------------------------------
// Pipelined mainloop (2-stage cp.async double buffer, 1 barrier per k-step).
// SCALE mode (gemm2): A source is raw E; on staging, scale by rinv for the
// MMA operand (P), and emit out_sm = E*rinv, out_sq = E*cinv in passing.
// ---------------------------------------------------------------------------
template <bool SCALE>
__device__ __forceinline__ void run_mainloop(
    const float* __restrict__ A, const float* __restrict__ Bsrc,
    float* dynsm, uint32_t sb, int n0, int tid, int tg, int sg,
    u64 acc2[16][2], const float* cinv, float rinv,
    float* __restrict__ out_sm, float* __restrict__ out_sq) {

    const int t   = tid >> 3;
    const int kkA = (tid & 7) * 2;
    const size_t nrow = (size_t)(n0 + t);
    const size_t arow = nrow * 512 + kkA;

    // ---- prologue: stage k0=0 into buffer 0 ----
    {
#pragma unroll
        for (int i = 0; i < 8; i++) {
            int chunk = tid + i * 256;
            int r = chunk >> 7, c = (chunk & 127) * 4;
            uint32_t dst = sb + (uint32_t)(2 * A_BUF + r * BS_LD + c) * 4;
            CP_ASYNC16(dst, Bsrc + (size_t)r * 512 + c);
        }
        CP_COMMIT();
        float2 av = *(const float2*)&A[arow];
        if (SCALE) {
            float2 sm2 = make_float2(av.x * rinv, av.y * rinv);
            *(float2*)&out_sm[arow] = sm2;
            *(float2*)&out_sq[arow] =
                make_float2(av.x * cinv[kkA], av.y * cinv[kkA + 1]);
            av = sm2;
        }
        float* As0 = dynsm;
        *(float2*)&As0[kkA * AS_LD + 2 * t]       = make_float2(av.x, av.x);
        *(float2*)&As0[(kkA + 1) * AS_LD + 2 * t] = make_float2(av.y, av.y);
        CP_WAIT0();
        __syncthreads();
    }

    int buf = 0;
    for (int k0 = 0; k0 < 512; k0 += BK) {
        float2 av;
        if (k0 < 512 - BK) {
            int nb = buf ^ 1;
#pragma unroll
            for (int i = 0; i < 8; i++) {
                int chunk = tid + i * 256;
                int r = chunk >> 7, c = (chunk & 127) * 4;
                uint32_t dst = sb + (uint32_t)(2 * A_BUF + nb * B_BUF + r * BS_LD + c) * 4;
                CP_ASYNC16(dst, Bsrc + (size_t)(k0 + BK + r) * 512 + c);
            }
            CP_COMMIT();
            av = *(const float2*)&A[arow + k0 + BK];
            if (SCALE) {
                int c0 = k0 + BK + kkA;
                float2 sm2 = make_float2(av.x * rinv, av.y * rinv);
                *(float2*)&out_sm[nrow * 512 + c0] = sm2;
                *(float2*)&out_sq[nrow * 512 + c0] =
                    make_float2(av.x * cinv[c0], av.y * cinv[c0 + 1]);
                av = sm2;
            }
        }
        {
            const float (*As2)[AS_LD] = (const float(*)[AS_LD])(dynsm + buf * A_BUF);
            const float (*Bs)[BS_LD]  = (const float(*)[BS_LD])(dynsm + 2 * A_BUF + buf * B_BUF);
            COMPUTE_KSTEP(As2, Bs, acc2, tg, sg)
        }
        if (k0 < 512 - BK) {
            float* Asn = dynsm + (buf ^ 1) * A_BUF;
            Asn[kkA * AS_LD + 2 * t]           = av.x;
            Asn[kkA * AS_LD + 2 * t + 1]       = av.x;
            Asn[(kkA + 1) * AS_LD + 2 * t]     = av.y;
            Asn[(kkA + 1) * AS_LD + 2 * t + 1] = av.y;
            CP_WAIT0();
        }
        __syncthreads();
        buf ^= 1;
    }
}

// ---------------------------------------------------------------------------
// K4: GEMM1 (score = q . mem^T) fused with exp and row/col sums.
// Stores raw E = exp(score) to out_sq; rowsums to g_rowsum; colsums to g_colsum.
// ---------------------------------------------------------------------------
__global__ void __launch_bounds__(256, 2)
k_gemm1(float* __restrict__ out_sq) {
    extern __shared__ float dynsm[];
    uint32_t sb = smem_u32(dynsm);
    float* rs = dynsm + EXTRA_OFF;        // 32 floats
    float* cs = dynsm + EXTRA_OFF + 32;   // 512 floats

    int tid = threadIdx.x;
    int sg = tid & 127;
    int tg = tid >> 7;
    int lane = tid & 31;
    int n0 = blockIdx.x * 32;

    u64 acc2[16][2];
#pragma unroll
    for (int i = 0; i < 16; i++) { acc2[i][0] = 0ull; acc2[i][1] = 0ull; }

    run_mainloop<false>(g_q, g_memT, dynsm, sb, n0, tid, tg, sg, acc2,
                        nullptr, 0.0f, nullptr, nullptr);

    // ---- epilogue: unpack, exp, row/col reductions, store raw E ----
    float acc[16][4];
#pragma unroll
    for (int i = 0; i < 16; i++) {
        unsigned lo, hi;
        UNPACK_F32X2(lo, hi, acc2[i][0]);
        acc[i][0] = __expf(__uint_as_float(lo));   // |score|<=1: no max-sub
        acc[i][1] = __expf(__uint_as_float(hi));
        UNPACK_F32X2(lo, hi, acc2[i][1]);
        acc[i][2] = __expf(__uint_as_float(lo));
        acc[i][3] = __expf(__uint_as_float(hi));
    }

    if (tid < 32) rs[tid] = 0.0f;
    cs[tid]       = 0.0f;
    cs[tid + 256] = 0.0f;
    __syncthreads();

    // Row sums: within a warp, every lane holds the SAME 16 tokens -> butterfly
#pragma unroll
    for (int i = 0; i < 16; i++) {
        float p = (acc[i][0] + acc[i][1]) + (acc[i][2] + acc[i][3]);
#pragma unroll
        for (int off = 16; off; off >>= 1)
            p += __shfl_xor_sync(0xFFFFFFFFu, p, off);
        if (lane == 0) atomicAdd(&rs[tg * 16 + i], p);
    }
    // Column sums: 4 slots/thread, 2-way contention per cs entry
    {
        float s0 = 0.0f, s1 = 0.0f, s2 = 0.0f, s3 = 0.0f;
#pragma unroll
        for (int i = 0; i < 16; i++) {
            s0 += acc[i][0]; s1 += acc[i][1]; s2 += acc[i][2]; s3 += acc[i][3];
        }
        atomicAdd(&cs[2 * sg],           s0);
        atomicAdd(&cs[2 * sg + 1],       s1);
        atomicAdd(&cs[256 + 2 * sg],     s2);
        atomicAdd(&cs[256 + 2 * sg + 1], s3);
    }
    __syncthreads();

    atomicAdd(&g_colsum[tid],       cs[tid]);
    atomicAdd(&g_colsum[tid + 256], cs[tid + 256]);
    if (tid < 32) g_rowsum[n0 + tid] = rs[tid];

#pragma unroll
    for (int i = 0; i < 16; i++) {
        size_t n = (size_t)(n0 + tg * 16 + i);
        *(float2*)&out_sq[n * Mm + 2 * sg]       = make_float2(acc[i][0], acc[i][1]);
        *(float2*)&out_sq[n * Mm + 256 + 2 * sg] = make_float2(acc[i][2], acc[i][3]);
    }
}

// ---------------------------------------------------------------------------
// K5: GEMM2 (upd = P . mem) with fused score finalization: while staging A
// (raw E rows, read once chip-wide), emits out_sm = E*rinv and out_sq = E*cinv.
// Output upd written in [B, D, H, W] layout via chunked smem transpose.
// ---------------------------------------------------------------------------
__global__ void __launch_bounds__(256, 2)
k_gemm2(const float* __restrict__ pmem,
        float* __restrict__ out_sq,
        float* __restrict__ out_sm,
        float* __restrict__ out_upd) {
    extern __shared__ float dynsm[];
    uint32_t sb = smem_u32(dynsm);
    float* sT   = dynsm + EXTRA_OFF;          // [32][33]
    float* cinv = dynsm + EXTRA_OFF + 1088;   // 512 floats

    int tid = threadIdx.x;
    int sg = tid & 127;
    int tg = tid >> 7;
    int n0 = blockIdx.x * 32;

    cinv[tid]       = 1.0f / g_colsum[tid];
    cinv[tid + 256] = 1.0f / g_colsum[tid + 256];
    __syncthreads();
    float rinv = 1.0f / g_rowsum[n0 + (tid >> 3)];

    u64 acc2[16][2];
#pragma unroll
    for (int i = 0; i < 16; i++) { acc2[i][0] = 0ull; acc2[i][1] = 0ull; }

    run_mainloop<true>(out_sq, pmem, dynsm, sb, n0, tid, tg, sg, acc2,
                       cinv, rinv, out_sm, out_sq);

    float acc[16][4];
#pragma unroll
    for (int i = 0; i < 16; i++) {
        unsigned lo, hi;
        UNPACK_F32X2(lo, hi, acc2[i][0]);
        acc[i][0] = __uint_as_float(lo);
        acc[i][1] = __uint_as_float(hi);
        UNPACK_F32X2(lo, hi, acc2[i][1]);
        acc[i][2] = __uint_as_float(lo);
        acc[i][3] = __uint_as_float(hi);
    }

    // Output transpose: upd[(b*D + d)*HW + hw], coalesced via 32-d chunks.
    // Thread owns d = {2sg, 2sg+1} (acc[..][0,1]) and {256+2sg, +1} (acc[..][2,3]).
    int b   = n0 / HWc;
    int hw0 = n0 % HWc;
    for (int c = 0; c < 16; c++) {
        int sgl  = (c & 7) * 16;          // sg range contributing to this chunk
        int half = (c >> 3) * 2;          // 0: low-256 slots, 2: high-256 slots
        if (sg >= sgl && sg < sgl + 16) {
            int dl0 = 2 * (sg - sgl);
#pragma unroll
            for (int i = 0; i < 16; i++) {
                int t = tg * 16 + i;
                sT[dl0 * 33 + t]       = acc[i][half];
                sT[(dl0 + 1) * 33 + t] = acc[i][half + 1];
            }
        }
        __syncthreads();
        {
            int t = tid & 31;
#pragma unroll
            for (int r = 0; r < 4; r++) {
                int dl = (tid >> 5) + r * 8;
                int d  = c * 32 + dl;
                out_upd[((size_t)(b * Dd + d)) * HWc + hw0 + t] = sT[dl * 33 + t];
            }
        }
        __syncthreads();
    }
}

// ---------------------------------------------------------------------------
extern "C" void kernel_launch(void* const* d_in, const int* in_sizes, int n_in,
                              void* d_out, int out_size) {
    const float* x    = (const float*)d_in[0];   // query_source [8,512,96,144]
    const float* pmem = (const float*)d_in[1];   // memory [512,512]
    float* out = (float*)d_out;

    const size_t ND = (size_t)Ntok * Dd;         // 56,623,104
    float* out_upd = out;                        // [B, D, H, W]
    float* out_sq  = out + ND;                   // softmax over tokens [N, M]
    float* out_sm  = out + 2 * ND;               // softmax over slots  [N, M]

    // Idempotent, capture-safe (not a stream op); needed for >48KB dynamic smem
    cudaFuncSetAttribute(k_gemm1, cudaFuncAttributeMaxDynamicSharedMemorySize, SMEM_DYN);
    cudaFuncSetAttribute(k_gemm2, cudaFuncAttributeMaxDynamicSharedMemorySize, SMEM_DYN);

    k_norm<<<Ntok / 256, 256>>>(x);
    k_prepT<<<dim3(16, 16), dim3(32, 8)>>>(pmem);
    k_qt<<<dim3(HWc / 32, Dd / 32, Bc), dim3(32, 8)>>>(x);
    k_gemm1<<<Ntok / 32, 256, SMEM_DYN>>>(out_sq);
    k_gemm2<<<Ntok / 32, 256, SMEM_DYN>>>(pmem, out_sq, out_sm, out_upd);
    (void)in_sizes; (void)n_in; (void)out_size;
}

// round 12
// speedup vs baseline: 1.5931x; 1.5931x over previous
#include <cuda_runtime.h>
#include <cuda_bf16.h>
#include <math.h>
#include <cstdint>

// Problem dims (fixed by the dataset)
#define Bc   8
#define Cc   512
#define Hc   96
#define Wc   144
#define HWc  (Hc * Wc)          // 13824
#define Ntok (Bc * HWc)         // 110592
#define Dd   512
#define Mm   512

// ---- GEMM tiling: CTA = 64 tok x 512 slots, 512 threads (16 warps) ----
// warp tile = 16 tok x 128 slots; K-chunk = 16 (bf16), 32 chunks.
// Smem: B panels 2buf x 2hl x 2panel x 512 rows x 16B = 64KB
//       A panels 2buf x 2hl x 2panel x  64 rows x 16B = 8KB
#define OFF_B     0
#define OFF_A     65536
#define OFF_CINV  73728
#define OFF_RSINV 75776
#define SMEM_DYN  76032

#define CP_ASYNC16(dst, src) \
    asm volatile("cp.async.ca.shared.global [%0], [%1], 16;" :: "r"(dst), "l"(src))
#define CP_COMMIT()  asm volatile("cp.async.commit_group;" ::: "memory")
#define CP_WAIT0()   asm volatile("cp.async.wait_group 0;" ::: "memory")

#define LDMX4(r, addr) \
    asm volatile("ldmatrix.sync.aligned.m8n8.x4.shared.b16 {%0,%1,%2,%3}, [%4];" \
        : "=r"((r)[0]), "=r"((r)[1]), "=r"((r)[2]), "=r"((r)[3]) : "r"(addr))

#define MMA16816(d, a, b0, b1) \
    asm volatile("mma.sync.aligned.m16n8k16.row.col.f32.bf16.bf16.f32 " \
        "{%0,%1,%2,%3}, {%4,%5,%6,%7}, {%8,%9}, {%0,%1,%2,%3};" \
        : "+f"((d)[0]), "+f"((d)[1]), "+f"((d)[2]), "+f"((d)[3]) \
        : "r"((a)[0]), "r"((a)[1]), "r"((a)[2]), "r"((a)[3]), "r"(b0), "r"(b1))

__device__ __forceinline__ uint32_t smem_u32(const void* p) {
    uint32_t a;
    asm("{ .reg .u64 t; cvta.to.shared.u64 t, %1; cvt.u32.u64 %0, t; }"
        : "=r"(a) : "l"(p));
    return a;
}

// Scratch (allocation-free rule: __device__ globals)
__device__ __nv_bfloat16 g_qhi[(size_t)Ntok * Dd];
__device__ __nv_bfloat16 g_qlo[(size_t)Ntok * Dd];
__device__ __nv_bfloat16 g_memhi[Mm * Dd],  g_memlo[Mm * Dd];   // [m][k]
__device__ __nv_bfloat16 g_memThi[Dd * Mm], g_memTlo[Dd * Mm];  // [d][m]
__device__ float g_inv[Ntok];
__device__ float g_rowsum[Ntok];
__device__ float g_colsum[Mm];

// ---------------------------------------------------------------------------
// K1: per-token inverse L2 norm over channels; zero colsum (replay idempotency)
// ---------------------------------------------------------------------------
__global__ void k_norm(const float* __restrict__ x) {
    int n = blockIdx.x * 256 + threadIdx.x;
    if (blockIdx.x == 0) {
        g_colsum[threadIdx.x]       = 0.0f;
        g_colsum[threadIdx.x + 256] = 0.0f;
    }
    if (n >= Ntok) return;
    int b = n / HWc, hw = n % HWc;
    const float* p = x + (size_t)b * Cc * HWc + hw;
    float s = 0.0f;
#pragma unroll 8
    for (int c = 0; c < Cc; c++) {
        float v = p[(size_t)c * HWc];
        s += v * v;
    }
    g_inv[n] = 1.0f / fmaxf(sqrtf(s), 1e-12f);
}

// ---------------------------------------------------------------------------
// K2: bf16 hi/lo split of memory, [m][k] and transposed [d][m]
// ---------------------------------------------------------------------------
__global__ void k_prep(const float* __restrict__ pmem) {
    int idx = blockIdx.x * 256 + threadIdx.x;   // 1024 blocks -> 262144
    int m = idx >> 9, d = idx & 511;
    float v = pmem[idx];
    __nv_bfloat16 h = __float2bfloat16(v);
    __nv_bfloat16 l = __float2bfloat16(v - __bfloat162float(h));
    g_memhi[idx] = h;           g_memlo[idx] = l;
    g_memThi[d * 512 + m] = h;  g_memTlo[d * 512 + m] = l;
}

// ---------------------------------------------------------------------------
// K3: transpose+normalize q -> bf16 hi/lo [N,D]
// ---------------------------------------------------------------------------
__global__ void k_qt(const float* __restrict__ x) {
    __shared__ float tile[32][33];
    int b   = blockIdx.z;
    int hw0 = blockIdx.x * 32;
    int d0  = blockIdx.y * 32;
    for (int r = threadIdx.y; r < 32; r += 8)
        tile[r][threadIdx.x] =
            x[((size_t)(b * Cc + d0 + r)) * HWc + hw0 + threadIdx.x];
    __syncthreads();
    for (int r = threadIdx.y; r < 32; r += 8) {
        int n = b * HWc + hw0 + r;
        float v = tile[threadIdx.x][r] * g_inv[n];
        __nv_bfloat16 h = __float2bfloat16(v);
        size_t off = (size_t)n * Dd + d0 + threadIdx.x;
        g_qhi[off] = h;
        g_qlo[off] = __float2bfloat16(v - __bfloat162float(h));
    }
}

// ---------------------------------------------------------------------------
// Staging: B tile (512 rows x 16 k, hi+lo) via cp.async, panel layout
// ---------------------------------------------------------------------------
__device__ __forceinline__ void stage_B(uint32_t sb, int buf,
                                        const __nv_bfloat16* __restrict__ Bhi,
                                        const __nv_bfloat16* __restrict__ Blo,
                                        int kc, int tid) {
#pragma unroll
    for (int it = 0; it < 4; it++) {
        int idx = tid + it * 512;          // 0..2047
        int hl = idx >> 10;
        int n  = (idx >> 1) & 511;
        int p  = idx & 1;
        const __nv_bfloat16* src = (hl ? Blo : Bhi) + (size_t)n * 512 + kc * 16 + p * 8;
        uint32_t dst = sb + OFF_B + buf * 32768 + hl * 16384 + p * 8192 + n * 16;
        CP_ASYNC16(dst, src);
    }
}

// A tile (64 rows x 16 k, hi+lo) via cp.async (gemm1)
__device__ __forceinline__ void stage_A1(uint32_t sb, int buf,
                                         const __nv_bfloat16* __restrict__ Ahi,
                                         const __nv_bfloat16* __restrict__ Alo,
                                         int n0, int kc, int tid) {
    if (tid < 256) {
        int hl = tid >> 7;
        int r  = (tid >> 1) & 63;
        int p  = tid & 1;
        const __nv_bfloat16* src = (hl ? Alo : Ahi) + (size_t)(n0 + r) * 512 + kc * 16 + p * 8;
        uint32_t dst = sb + OFF_A + buf * 4096 + hl * 2048 + p * 1024 + r * 16;
        CP_ASYNC16(dst, src);
    }
}

// A tile for gemm2: read raw E (f32), convert to bf16 hi/lo, and in passing
// emit out_sm = E*rinv, out_sq = E*cinv (each E element touched exactly once).
__device__ __forceinline__ void stage_A2(char* dyn, int buf,
                                         float* __restrict__ E,
                                         float* __restrict__ out_sm,
                                         const float* rs_inv, const float* cinv_s,
                                         int n0, int kc, int tid) {
    int r  = tid >> 3;
    int kk = (tid & 7) * 2;
    size_t off = (size_t)(n0 + r) * 512 + kc * 16 + kk;
    float2 e2 = *(const float2*)&E[off];
    float ri = rs_inv[r];
    *(float2*)&out_sm[off] = make_float2(e2.x * ri, e2.y * ri);
    int cgl = kc * 16 + kk;
    *(float2*)&E[off] = make_float2(e2.x * cinv_s[cgl], e2.y * cinv_s[cgl + 1]);
    __nv_bfloat16 h0 = __float2bfloat16(e2.x), h1 = __float2bfloat16(e2.y);
    __nv_bfloat16 l0 = __float2bfloat16(e2.x - __bfloat162float(h0));
    __nv_bfloat16 l1 = __float2bfloat16(e2.y - __bfloat162float(h1));
    int p = kk >> 3, c = kk & 7;
    char* d0 = dyn + OFF_A + buf * 4096 + p * 1024 + r * 16 + c * 2;
    *(__nv_bfloat162*)d0          = __halves2bfloat162(h0, h1);
    *(__nv_bfloat162*)(d0 + 2048) = __halves2bfloat162(l0, l1);
}

// ---------------------------------------------------------------------------
// One K-chunk of compute: 18 ldmatrix.x4 + 48 mma (error-compensated bf16x3)
// ---------------------------------------------------------------------------
__device__ __forceinline__ void chunk_compute(uint32_t sb, int buf, int tg,
                                              int sgp, int lane,
                                              float acc[16][4]) {
    uint32_t ah[4], al[4];
    uint32_t a_addr = sb + OFF_A + buf * 4096 + (lane >> 4) * 1024
                    + (tg * 16 + (lane & 15)) * 16;
    LDMX4(ah, a_addr);
    LDMX4(al, a_addr + 2048);

    int g = lane >> 3;
    uint32_t b_off = (uint32_t)((g & 1) * 8192 + ((g >> 1) * 8 + (lane & 7)) * 16);
    uint32_t b_hi = sb + OFF_B + buf * 32768 + b_off;
#pragma unroll
    for (int jp = 0; jp < 8; jp++) {
        uint32_t nb = (uint32_t)((sgp * 128 + jp * 16) * 16);
        uint32_t bh[4], bl[4];
        LDMX4(bh, b_hi + nb);
        LDMX4(bl, b_hi + 16384 + nb);
        MMA16816(acc[2 * jp],     ah, bh[0], bh[1]);
        MMA16816(acc[2 * jp],     ah, bl[0], bl[1]);
        MMA16816(acc[2 * jp],     al, bh[0], bh[1]);
        MMA16816(acc[2 * jp + 1], ah, bh[2], bh[3]);
        MMA16816(acc[2 * jp + 1], ah, bl[2], bl[3]);
        MMA16816(acc[2 * jp + 1], al, bh[2], bh[3]);
    }
}

// ---------------------------------------------------------------------------
// K4: GEMM1 -> out_sq = E = exp(q . mem^T)   (raw, unnormalized)
// ---------------------------------------------------------------------------
__global__ void __launch_bounds__(512, 1)
k_g1(float* __restrict__ out_sq) {
    extern __shared__ char dyn[];
    uint32_t sb = smem_u32(dyn);
    int tid = threadIdx.x, lane = tid & 31, wid = tid >> 5;
    int tg = wid & 3, sgp = wid >> 2;
    int n0 = blockIdx.x * 64;

    float acc[16][4];
#pragma unroll
    for (int j = 0; j < 16; j++)
#pragma unroll
        for (int q = 0; q < 4; q++) acc[j][q] = 0.0f;

    stage_B(sb, 0, g_memhi, g_memlo, 0, tid);
    stage_A1(sb, 0, g_qhi, g_qlo, n0, 0, tid);
    CP_COMMIT(); CP_WAIT0(); __syncthreads();

    int buf = 0;
    for (int kc = 0; kc < 32; kc++) {
        if (kc < 31) {
            stage_B(sb, buf ^ 1, g_memhi, g_memlo, kc + 1, tid);
            stage_A1(sb, buf ^ 1, g_qhi, g_qlo, n0, kc + 1, tid);
            CP_COMMIT();
        }
        chunk_compute(sb, buf, tg, sgp, lane, acc);
        if (kc < 31) CP_WAIT0();
        __syncthreads();
        buf ^= 1;
    }

    // epilogue: E = exp(score) (|score|<=1: no max-sub), 32B-sector stores
    int row = n0 + tg * 16 + (lane >> 2);
#pragma unroll
    for (int j = 0; j < 16; j++) {
        int col = sgp * 128 + j * 8 + (lane & 3) * 2;
        *(float2*)&out_sq[(size_t)row * 512 + col] =
            make_float2(__expf(acc[j][0]), __expf(acc[j][1]));
        *(float2*)&out_sq[(size_t)(row + 8) * 512 + col] =
            make_float2(__expf(acc[j][2]), __expf(acc[j][3]));
    }
}

// ---------------------------------------------------------------------------
// K5: stream E once -> per-token rowsums (exact) + colsum atomics
// ---------------------------------------------------------------------------
__global__ void __launch_bounds__(256)
k_sums(const float* __restrict__ E) {
    __shared__ float rp[64];
    int tid = threadIdx.x, lane = tid & 31, w = tid >> 5;
    int n0 = blockIdx.x * 64;
    if (tid < 64) rp[tid] = 0.0f;
    __syncthreads();

    int c0 = w * 64 + lane * 2;
    float cs0 = 0.0f, cs1 = 0.0f;
    for (int t = 0; t < 64; t++) {
        float2 v = *(const float2*)&E[(size_t)(n0 + t) * 512 + c0];
        cs0 += v.x; cs1 += v.y;
        float s = v.x + v.y;
#pragma unroll
        for (int off = 16; off; off >>= 1)
            s += __shfl_xor_sync(0xFFFFFFFFu, s, off);
        if (lane == 0) atomicAdd(&rp[t], s);
    }
    __syncthreads();
    if (tid < 64) g_rowsum[n0 + tid] = rp[tid];
    atomicAdd(&g_colsum[c0],     cs0);
    atomicAdd(&g_colsum[c0 + 1], cs1);
}

// ---------------------------------------------------------------------------
// K6: GEMM2 upd = (E*rinv) . mem, fused score finalization in A-staging.
// Output written in [B, D, H, W] layout via smem transpose chunks.
// ---------------------------------------------------------------------------
__global__ void __launch_bounds__(512, 1)
k_g2(float* __restrict__ out_sq,       // raw E in, E*cinv out
     float* __restrict__ out_sm,
     float* __restrict__ out_upd) {
    extern __shared__ char dyn[];
    uint32_t sb = smem_u32(dyn);
    float* cinv_s = (float*)(dyn + OFF_CINV);
    float* rs_inv = (float*)(dyn + OFF_RSINV);
    int tid = threadIdx.x, lane = tid & 31, wid = tid >> 5;
    int tg = wid & 3, sgp = wid >> 2;
    int n0 = blockIdx.x * 64;

    cinv_s[tid] = 1.0f / g_colsum[tid];
    if (tid < 64) rs_inv[tid] = 1.0f / g_rowsum[n0 + tid];
    __syncthreads();

    float acc[16][4];
#pragma unroll
    for (int j = 0; j < 16; j++)
#pragma unroll
        for (int q = 0; q < 4; q++) acc[j][q] = 0.0f;

    stage_B(sb, 0, g_memThi, g_memTlo, 0, tid);
    CP_COMMIT();
    stage_A2(dyn, 0, out_sq, out_sm, rs_inv, cinv_s, n0, 0, tid);
    CP_WAIT0(); __syncthreads();

    int buf = 0;
    for (int kc = 0; kc < 32; kc++) {
        if (kc < 31) {
            stage_B(sb, buf ^ 1, g_memThi, g_memTlo, kc + 1, tid);
            CP_COMMIT();
            stage_A2(dyn, buf ^ 1, out_sq, out_sm, rs_inv, cinv_s, n0, kc + 1, tid);
        }
        chunk_compute(sb, buf, tg, sgp, lane, acc);
        if (kc < 31) CP_WAIT0();
        __syncthreads();
        buf ^= 1;
    }

    // scale rows by rinv (upd = P.mem with P = E*rinv)
    {
        float r0 = rs_inv[tg * 16 + (lane >> 2)];
        float r1 = rs_inv[tg * 16 + (lane >> 2) + 8];
#pragma unroll
        for (int j = 0; j < 16; j++) {
            acc[j][0] *= r0; acc[j][1] *= r0;
            acc[j][2] *= r1; acc[j][3] *= r1;
        }
    }

    // transpose to [B, D, H, W]
    float* sT = (float*)dyn;                  // reuse B region: [32][68]
    int b   = n0 / HWc;
    int hw0 = n0 % HWc;
    int tok0 = tg * 16 + (lane >> 2);
    for (int sg_it = 0; sg_it < 4; sg_it++) {
        for (int dc = 0; dc < 4; dc++) {
            if (sgp == sg_it) {
#pragma unroll
                for (int jj = 0; jj < 4; jj++) {
                    int j  = dc * 4 + jj;
                    int dl = jj * 8 + (lane & 3) * 2;
                    sT[dl * 68 + tok0]           = acc[j][0];
                    sT[(dl + 1) * 68 + tok0]     = acc[j][1];
                    sT[dl * 68 + tok0 + 8]       = acc[j][2];
                    sT[(dl + 1) * 68 + tok0 + 8] = acc[j][3];
                }
            }
            __syncthreads();
            {
                int dl  = tid >> 4;
                int hwl = (tid & 15) * 4;
                int d   = sg_it * 128 + dc * 32 + dl;
                float4 v = make_float4(sT[dl * 68 + hwl],     sT[dl * 68 + hwl + 1],
                                       sT[dl * 68 + hwl + 2], sT[dl * 68 + hwl + 3]);
                *(float4*)&out_upd[((size_t)(b * Dd + d)) * HWc + hw0 + hwl] = v;
            }
            __syncthreads();
        }
    }
}

// ---------------------------------------------------------------------------
extern "C" void kernel_launch(void* const* d_in, const int* in_sizes, int n_in,
                              void* d_out, int out_size) {
    const float* x    = (const float*)d_in[0];   // query_source [8,512,96,144]
    const float* pmem = (const float*)d_in[1];   // memory [512,512]
    float* out = (float*)d_out;

    const size_t ND = (size_t)Ntok * Dd;         // 56,623,104
    float* out_upd = out;                        // [B, D, H, W]
    float* out_sq  = out + ND;                   // softmax over tokens [N, M]
    float* out_sm  = out + 2 * ND;               // softmax over slots  [N, M]

    // Idempotent, capture-safe; needed for >48KB dynamic smem
    cudaFuncSetAttribute(k_g1, cudaFuncAttributeMaxDynamicSharedMemorySize, SMEM_DYN);
    cudaFuncSetAttribute(k_g2, cudaFuncAttributeMaxDynamicSharedMemorySize, SMEM_DYN);

    k_norm<<<Ntok / 256, 256>>>(x);
    k_prep<<<(Mm * Dd) / 256, 256>>>(pmem);
    k_qt<<<dim3(HWc / 32, Dd / 32, Bc), dim3(32, 8)>>>(x);
    k_g1<<<Ntok / 64, 512, SMEM_DYN>>>(out_sq);
    k_sums<<<Ntok / 64, 256>>>(out_sq);
    k_g2<<<Ntok / 64, 512, SMEM_DYN>>>(out_sq, out_sm, out_upd);
    (void)in_sizes; (void)n_in; (void)out_size;
}